// round 16
// baseline (speedup 1.0000x reference)
#include <cuda_runtime.h>
#include <cuda_fp16.h>
#include <cuda_bf16.h>
#include <cstdint>

// Problem constants
#define BB 4
#define TT 2048
#define CC 1024
#define HH 16
#define DD 64
#define FFD 4096
#define NTOK (BB*TT)          // 8192
#define LOG2E 1.4426950408889634f

// ---------------- scratch (device globals; no allocation allowed) -----------
__device__ uint32_t g_ln16 [NTOK * CC / 2];          // LN1 out, fp16 pairs
__device__ uint32_t g_lnH2 [NTOK * CC / 2];          // LN2 out, fp16 pairs
__device__ uint32_t g_lnH  [NTOK * CC / 2];          // LN1 out, bf16 hi pairs
__device__ uint32_t g_lnL  [NTOK * CC / 2];          // LN1 out, bf16 lo pairs
__device__ uint32_t g_qH   [BB*HH * TT * DD / 2];    // Q bf16 hi pairs (x log2e)
__device__ uint32_t g_qL   [BB*HH * TT * DD / 2];
__device__ __nv_bfloat16 g_kH [BB*HH * TT * DD];
__device__ __nv_bfloat16 g_kL [BB*HH * TT * DD];
__device__ __half   g_vT   [BB*HH * DD * TT];        // V fp16 TRANSPOSED [bh][d][t]
__device__ uint32_t g_attnc[NTOK * CC / 2];          // fp16 pairs
__device__ float    g_x1   [NTOK * CC];
__device__ uint32_t g_ff1  [NTOK * FFD / 2];         // fp16 pairs
__device__ __nv_bfloat16 g_wqkTH[2*CC * CC];         // Wq^T,Wk^T bf16 hi
__device__ __nv_bfloat16 g_wqkTL[2*CC * CC];
__device__ __half   g_wvT  [CC * CC];                // Wv^T fp16
__device__ __half   g_woT  [CC * CC];
__device__ __half   g_w1T  [FFD * CC];
__device__ __half   g_w2T  [CC * FFD];

// ---------------- low-level helpers -----------------------------------------
__device__ __forceinline__ uint32_t smem_u32(const void* p) {
    uint32_t a;
    asm("{ .reg .u64 t; cvta.to.shared.u64 t, %1; cvt.u32.u64 %0, t; }"
        : "=r"(a) : "l"(p));
    return a;
}
__device__ __forceinline__ void cp16(uint32_t s, const void* g) {
    asm volatile("cp.async.cg.shared.global [%0], [%1], 16;" :: "r"(s), "l"(g));
}
__device__ __forceinline__ void cpcommit() {
    asm volatile("cp.async.commit_group;" ::: "memory");
}
template <int N>
__device__ __forceinline__ void cpwait() {
    asm volatile("cp.async.wait_group %0;" :: "n"(N) : "memory");
}
__device__ __forceinline__ void ldmx4(uint32_t* r, uint32_t addr) {
    asm volatile(
        "ldmatrix.sync.aligned.m8n8.x4.shared.b16 {%0,%1,%2,%3}, [%4];"
        : "=r"(r[0]), "=r"(r[1]), "=r"(r[2]), "=r"(r[3]) : "r"(addr));
}
__device__ __forceinline__ void mma16b(float* d, uint32_t a0, uint32_t a1,
                                       uint32_t a2, uint32_t a3,
                                       uint32_t b0, uint32_t b1) {
    asm volatile(
        "mma.sync.aligned.m16n8k16.row.col.f32.bf16.bf16.f32 "
        "{%0,%1,%2,%3}, {%4,%5,%6,%7}, {%8,%9}, {%0,%1,%2,%3};"
        : "+f"(d[0]), "+f"(d[1]), "+f"(d[2]), "+f"(d[3])
        : "r"(a0), "r"(a1), "r"(a2), "r"(a3), "r"(b0), "r"(b1));
}
__device__ __forceinline__ void mma16h(float* d, uint32_t a0, uint32_t a1,
                                       uint32_t a2, uint32_t a3,
                                       uint32_t b0, uint32_t b1) {
    asm volatile(
        "mma.sync.aligned.m16n8k16.row.col.f32.f16.f16.f32 "
        "{%0,%1,%2,%3}, {%4,%5,%6,%7}, {%8,%9}, {%0,%1,%2,%3};"
        : "+f"(d[0]), "+f"(d[1]), "+f"(d[2]), "+f"(d[3])
        : "r"(a0), "r"(a1), "r"(a2), "r"(a3), "r"(b0), "r"(b1));
}
__device__ __forceinline__ uint32_t packbf(float x, float y) {
    __nv_bfloat162 t = __floats2bfloat162_rn(x, y);
    return *reinterpret_cast<uint32_t*>(&t);
}
__device__ __forceinline__ uint32_t packh(float x, float y) {
    __half2 t = __floats2half2_rn(x, y);
    return *reinterpret_cast<uint32_t*>(&t);
}
__device__ __forceinline__ void splitbf(float x, float y, uint32_t& hp, uint32_t& lp) {
    float hx = __bfloat162float(__float2bfloat16(x));
    float hy = __bfloat162float(__float2bfloat16(y));
    hp = packbf(hx, hy);
    lp = packbf(x - hx, y - hy);
}

// ================= QK GEMM: bf16x3, 512 threads, warp tile 32x32 =============
#define QST 4
#define QPADU 20
#define QTILEU (128*QPADU)
#define QSMEM_BYTES (4*QST*QTILEU*4)       // 163840

__global__ void __launch_bounds__(512, 1) qk_gemm(
    const __nv_bfloat16* __restrict__ AH, const __nv_bfloat16* __restrict__ AL,
    const __nv_bfloat16* __restrict__ BH, const __nv_bfloat16* __restrict__ BL,
    uint32_t* __restrict__ qHo, uint32_t* __restrict__ qLo,
    uint32_t* __restrict__ kHo, uint32_t* __restrict__ kLo)
{
    extern __shared__ uint32_t smq[];
    uint32_t aH = smem_u32(smq);
    uint32_t aL = aH + QST * QTILEU * 4;
    uint32_t bH = aH + 2 * QST * QTILEU * 4;
    uint32_t bL = aH + 3 * QST * QTILEU * 4;
    int tid = threadIdx.x, wid = tid >> 5, lane = tid & 31;
    int r = lane >> 2, c = lane & 3;
    int wm = (wid & 3) * 32, wn = (wid >> 2) * 32;
    int row0 = blockIdx.y * 128, col0 = blockIdx.x * 128;

    int rA  = (lane & 7) + ((lane >> 3) & 1) * 8;
    int kqA = (lane >> 4) * 4;
    int rB  = (lane & 7);
    int sB  = (lane >> 4);
    int kqB = ((lane >> 3) & 1) * 4;

    auto loadst = [&](int slot, int kt) {
        int k0 = kt * 32;
        int row = tid >> 2, ch = tid & 3;
        uint32_t doff = (uint32_t)(slot * QTILEU + row * QPADU + ch * 4) * 4;
        size_t sa = (size_t)(row0 + row) * CC + k0 + ch * 8;
        size_t sb = (size_t)(col0 + row) * CC + k0 + ch * 8;
        cp16(aH + doff, AH + sa);
        cp16(aL + doff, AL + sa);
        cp16(bH + doff, BH + sb);
        cp16(bL + doff, BL + sb);
    };

    float acc[2][4][4] = {};
    loadst(0, 0); cpcommit();
    loadst(1, 1); cpcommit();

    for (int kt = 0; kt < 32; kt++) {
        if (kt + 2 < 32) loadst((kt + 2) & 3, kt + 2);
        cpcommit();
        cpwait<2>();
        __syncthreads();
        uint32_t stoff = (uint32_t)((kt & 3) * QTILEU) * 4;
#pragma unroll
        for (int s = 0; s < 2; s++) {
            int pb = s * 8;
            uint32_t ah[2][4], al[2][4], bhp[2][4], blp[2][4];
#pragma unroll
            for (int mt = 0; mt < 2; mt++) {
                uint32_t off = (uint32_t)((wm + mt * 16 + rA) * QPADU + pb + kqA) * 4;
                ldmx4(ah[mt], aH + stoff + off);
                ldmx4(al[mt], aL + stoff + off);
            }
#pragma unroll
            for (int j = 0; j < 2; j++) {
                uint32_t off = (uint32_t)((wn + (2 * j + sB) * 8 + rB) * QPADU + pb + kqB) * 4;
                ldmx4(bhp[j], bH + stoff + off);
                ldmx4(blp[j], bL + stoff + off);
            }
#pragma unroll
            for (int mt = 0; mt < 2; mt++)
#pragma unroll
                for (int j = 0; j < 2; j++)
#pragma unroll
                    for (int h2 = 0; h2 < 2; h2++) {
                        float* a4 = acc[mt][2 * j + h2];
                        uint32_t b0 = bhp[j][2 * h2], b1 = bhp[j][2 * h2 + 1];
                        mma16b(a4, ah[mt][0], ah[mt][1], ah[mt][2], ah[mt][3], b0, b1);
                        mma16b(a4, al[mt][0], al[mt][1], al[mt][2], al[mt][3], b0, b1);
                        mma16b(a4, ah[mt][0], ah[mt][1], ah[mt][2], ah[mt][3],
                               blp[j][2 * h2], blp[j][2 * h2 + 1]);
                    }
        }
    }

    // epilogue: scatter q (bf16 H/L, pre-scaled by log2e), k (bf16 H/L)
#pragma unroll
    for (int mt = 0; mt < 2; mt++) {
        int rg0 = row0 + wm + mt * 16 + r;
#pragma unroll
        for (int nt = 0; nt < 4; nt++) {
            int cg = col0 + wn + nt * 8 + 2 * c;
            int sel = cg >> 10;
            int h = (cg >> 6) & 15;
            int d = cg & 63;
            uint32_t* H = sel ? kHo : qHo;
            uint32_t* L = sel ? kLo : qLo;
            float scale = sel ? 1.f : LOG2E;
#pragma unroll
            for (int half_ = 0; half_ < 2; half_++) {
                int rg = rg0 + half_ * 8;
                int bb = rg >> 11, t = rg & 2047;
                size_t ofs = (((size_t)(bb * HH + h) * TT + t) << 6) + d;
                uint32_t hp, lp;
                splitbf(acc[mt][nt][half_ * 2 + 0] * scale,
                        acc[mt][nt][half_ * 2 + 1] * scale, hp, lp);
                H[ofs >> 1] = hp;
                L[ofs >> 1] = lp;
            }
        }
    }
}

// ================= fp16 GEMM (V-proj, Wo, W1, W2), 512 threads ===============
// 5 stages, prefetch distance 3 (deeper MLP on the cp.async chain; these
// kernels are LSU/latency-bound at 1 block/SM).
#define HST 5
#define HPADU 20
#define HTILEU (128*HPADU)
#define HSMEM_BYTES (2*HST*HTILEU*4)       // 102400

template <int NN, int KK, int EPI>
__global__ void __launch_bounds__(512, 1) hgemm(
    const uint32_t* __restrict__ A, const uint32_t* __restrict__ BT,
    void* __restrict__ Op,
    const float* __restrict__ bias, const float* __restrict__ res)
{
    extern __shared__ uint32_t smh[];
    uint32_t aS = smem_u32(smh);
    uint32_t bS = aS + HST * HTILEU * 4;
    int tid = threadIdx.x, wid = tid >> 5, lane = tid & 31;
    int r = lane >> 2, c = lane & 3;
    int wm = (wid & 3) * 32, wn = (wid >> 2) * 32;
    int row0 = blockIdx.y * 128, col0 = blockIdx.x * 128;
    constexpr int KU = KK / 2;
    const uint32_t* Ag = A + (size_t)row0 * KU;
    const uint32_t* Bg = BT + (size_t)col0 * KU;

    int rA  = (lane & 7) + ((lane >> 3) & 1) * 8;
    int kqA = (lane >> 4) * 4;
    int rB  = (lane & 7);
    int sB  = (lane >> 4);
    int kqB = ((lane >> 3) & 1) * 4;

    auto loadst = [&](int slot, int kt) {
        int k0 = kt * 16;
        int row = tid >> 2, ch = tid & 3;
        uint32_t doff = (uint32_t)(slot * HTILEU + row * HPADU + ch * 4) * 4;
        cp16(aS + doff, Ag + (size_t)row * KU + k0 + ch * 4);
        cp16(bS + doff, Bg + (size_t)row * KU + k0 + ch * 4);
    };

    float acc[2][4][4] = {};
    constexpr int KT = KK / 32;
    loadst(0, 0); cpcommit();
    loadst(1, 1); cpcommit();
    loadst(2, 2); cpcommit();

    int slot = 0;
    for (int kt = 0; kt < KT; kt++) {
        if (kt + 3 < KT) loadst((kt + 3) % HST, kt + 3);
        cpcommit();
        cpwait<3>();
        __syncthreads();     // write stages (kt+3)%5 / skew-1 (kt+4)%5 never
                             // alias read stage kt%5
        uint32_t stoff = (uint32_t)(slot * HTILEU) * 4;
        slot = (slot + 1 == HST) ? 0 : slot + 1;
#pragma unroll
        for (int s = 0; s < 2; s++) {
            int pb = s * 8;
            uint32_t a[2][4], bp[2][4];
#pragma unroll
            for (int mt = 0; mt < 2; mt++) {
                uint32_t off = (uint32_t)((wm + mt * 16 + rA) * HPADU + pb + kqA) * 4;
                ldmx4(a[mt], aS + stoff + off);
            }
#pragma unroll
            for (int j = 0; j < 2; j++) {
                uint32_t off = (uint32_t)((wn + (2 * j + sB) * 8 + rB) * HPADU + pb + kqB) * 4;
                ldmx4(bp[j], bS + stoff + off);
            }
#pragma unroll
            for (int mt = 0; mt < 2; mt++)
#pragma unroll
                for (int j = 0; j < 2; j++)
#pragma unroll
                    for (int h2 = 0; h2 < 2; h2++)
                        mma16h(acc[mt][2 * j + h2], a[mt][0], a[mt][1], a[mt][2],
                               a[mt][3], bp[j][2 * h2], bp[j][2 * h2 + 1]);
        }
    }

#pragma unroll
    for (int mt = 0; mt < 2; mt++) {
        int rg0 = row0 + wm + mt * 16 + r;
#pragma unroll
        for (int nt = 0; nt < 4; nt++) {
            int cg = col0 + wn + nt * 8 + 2 * c;
#pragma unroll
            for (int half_ = 0; half_ < 2; half_++) {
                int rg = rg0 + half_ * 8;
                float v0 = acc[mt][nt][half_ * 2 + 0];
                float v1 = acc[mt][nt][half_ * 2 + 1];
                if (EPI == 3) {
                    int h = cg >> 6, d = cg & 63;
                    int bb = rg >> 11, t = rg & 2047;
                    __half* vp = (__half*)Op +
                        ((size_t)(bb * HH + h) * DD + d) * TT + t;
                    vp[0]  = __float2half(v0);
                    vp[TT] = __float2half(v1);
                } else {
                    size_t off = (size_t)rg * NN + cg;
                    float2 b2 = *(const float2*)(bias + cg);
                    if (EPI == 1) {
                        float2 r2 = *(const float2*)(res + off);
                        *(float2*)((float*)Op + off) =
                            make_float2(v0 + b2.x + r2.x, v1 + b2.y + r2.y);
                    } else {
                        ((uint32_t*)Op)[off >> 1] =
                            packh(fmaxf(v0 + b2.x, 0.f), fmaxf(v1 + b2.y, 0.f));
                    }
                }
            }
        }
    }
}

// ================= flash attention: bf16x3 QK^T (log2 domain), fp16 PV =======
#define KPADU 36
#define VPADU 36
#define PPADU 36
#define QPADF 36
#define F_KH 0
#define F_KL 18432
#define F_V  36864
#define F_QH 55296
#define F_QL 73728
#define F_PS 92160
#define FSMEM_BYTES 110592

__global__ void __launch_bounds__(256, 2) flash_kernel(
    const uint32_t* __restrict__ qH, const uint32_t* __restrict__ qL,
    const __nv_bfloat16* __restrict__ kH, const __nv_bfloat16* __restrict__ kL,
    const uint32_t* __restrict__ vT, uint32_t* __restrict__ attnc)
{
    extern __shared__ char smc[];
    uint32_t base = smem_u32(smc);

    int tid = threadIdx.x, wid = tid >> 5, lane = tid & 31;
    int r = lane >> 2, c = lane & 3;
    int qt = (int)gridDim.x - 1 - (int)blockIdx.x;   // longest blocks first
    int bh = blockIdx.y;
    int t0 = qt * 128;
    int wq = wid * 16;
    const uint32_t* qH32 = qH + (size_t)bh * TT * 32;
    const uint32_t* qL32 = qL + (size_t)bh * TT * 32;
    const __nv_bfloat16* kHb = kH + (size_t)bh * TT * DD;
    const __nv_bfloat16* kLb = kL + (size_t)bh * TT * DD;
    const uint32_t* vT32 = vT + (size_t)bh * DD * (TT / 2);

    int rA  = (lane & 7) + ((lane >> 3) & 1) * 8;
    int kqA = (lane >> 4) * 4;
    int rB  = (lane & 7);
    int sB  = (lane >> 4);
    int kqB = ((lane >> 3) & 1) * 4;

    // stage Q tile (hi/lo) into SMEM via cp.async (rides first commit group)
    {
        uint32_t qhS = base + F_QH, qlS = base + F_QL;
#pragma unroll
        for (int i = 0; i < 4; i++) {
            int j = tid + i * 256;
            int row = j >> 3, ch = j & 7;
            uint32_t doff = (uint32_t)(row * QPADF + ch * 4) * 4;
            size_t src = (size_t)(t0 + row) * 32 + ch * 4;
            cp16(qhS + doff, qH32 + src);
            cp16(qlS + doff, qL32 + src);
        }
    }

    auto loadkv = [&](int buf, int it) {
        int s0 = it * 64;
        uint32_t kh = base + F_KH + buf * 9216;
        uint32_t kl = base + F_KL + buf * 9216;
        uint32_t vs = base + F_V + buf * 9216;
#pragma unroll
        for (int i = 0; i < 2; i++) {
            int j = tid + i * 256;
            int row = j >> 3, ch = j & 7;
            uint32_t doff = (uint32_t)(row * KPADU + ch * 4) * 4;
            size_t src = (size_t)(s0 + row) * DD + ch * 8;
            cp16(kh + doff, kHb + src);
            cp16(kl + doff, kLb + src);
        }
#pragma unroll
        for (int i = 0; i < 2; i++) {
            int j = tid + i * 256;
            int row = j >> 3, ch = j & 7;
            cp16(vs + (uint32_t)(row * VPADU + ch * 4) * 4,
                 vT32 + (size_t)row * (TT / 2) + (s0 >> 1) + ch * 4);
        }
    };

    int nst = 2 * qt + 2;
    loadkv(0, 0); cpcommit();

    float m0 = -1e30f, m1 = -1e30f, l0 = 0.f, l1 = 0.f;
    float O[8][4] = {};
    uint32_t pwbase = base + F_PS + (uint32_t)(wq * PPADU) * 4;
    uint32_t qhW = base + F_QH + (uint32_t)(wq * QPADF) * 4;
    uint32_t qlW = base + F_QL + (uint32_t)(wq * QPADF) * 4;

    for (int it = 0; it < nst; it++) {
        if (it + 1 < nst) loadkv((it + 1) & 1, it + 1);
        cpcommit();
        cpwait<1>();
        __syncthreads();
        int s0 = it * 64;
        if (s0 <= t0 + wq + 15) {
            uint32_t khB = base + F_KH + (it & 1) * 9216;
            uint32_t klB = base + F_KL + (it & 1) * 9216;
            uint32_t vsB = base + F_V + (it & 1) * 9216;

            // ---- S = Q K^T (bf16x3, log2 domain) ----
            float S[8][4] = {};
#pragma unroll
            for (int s = 0; s < 4; s++) {
                uint32_t qh4[4], ql4[4];
                uint32_t qoff = (uint32_t)(rA * QPADF + s * 8 + kqA) * 4;
                ldmx4(qh4, qhW + qoff);
                ldmx4(ql4, qlW + qoff);
#pragma unroll
                for (int j = 0; j < 4; j++) {
                    uint32_t off = (uint32_t)(((2 * j + sB) * 8 + rB) * KPADU + s * 8 + kqB) * 4;
                    uint32_t bh4[4], bl4[4];
                    ldmx4(bh4, khB + off);
                    ldmx4(bl4, klB + off);
#pragma unroll
                    for (int h2 = 0; h2 < 2; h2++) {
                        float* s4 = S[2 * j + h2];
                        uint32_t b0 = bh4[2 * h2], b1 = bh4[2 * h2 + 1];
                        mma16b(s4, qh4[0], qh4[1], qh4[2], qh4[3], b0, b1);
                        mma16b(s4, ql4[0], ql4[1], ql4[2], ql4[3], b0, b1);
                        mma16b(s4, qh4[0], qh4[1], qh4[2], qh4[3],
                               bl4[2 * h2], bl4[2 * h2 + 1]);
                    }
                }
            }

            // ---- causal mask ----
            if (s0 + 63 > t0 + wq) {
#pragma unroll
                for (int nt = 0; nt < 8; nt++)
#pragma unroll
                    for (int jj = 0; jj < 4; jj++) {
                        int scol = s0 + nt * 8 + 2 * c + (jj & 1);
                        int trow = t0 + wq + r + ((jj >> 1) << 3);
                        if (scol > trow) S[nt][jj] = -1e30f;
                    }
            }

            // ---- online softmax (log2 domain) ----
            float mx0 = -1e30f, mx1 = -1e30f;
#pragma unroll
            for (int nt = 0; nt < 8; nt++) {
                mx0 = fmaxf(mx0, fmaxf(S[nt][0], S[nt][1]));
                mx1 = fmaxf(mx1, fmaxf(S[nt][2], S[nt][3]));
            }
            mx0 = fmaxf(mx0, __shfl_xor_sync(0xffffffffu, mx0, 1));
            mx0 = fmaxf(mx0, __shfl_xor_sync(0xffffffffu, mx0, 2));
            mx1 = fmaxf(mx1, __shfl_xor_sync(0xffffffffu, mx1, 1));
            mx1 = fmaxf(mx1, __shfl_xor_sync(0xffffffffu, mx1, 2));
            float nm0 = fmaxf(m0, mx0), nm1 = fmaxf(m1, mx1);
            float al0 = exp2f(m0 - nm0), al1 = exp2f(m1 - nm1);
            m0 = nm0; m1 = nm1;
            float su0 = 0.f, su1 = 0.f;
#pragma unroll
            for (int nt = 0; nt < 8; nt++) {
                S[nt][0] = exp2f(S[nt][0] - nm0);
                S[nt][1] = exp2f(S[nt][1] - nm0);
                S[nt][2] = exp2f(S[nt][2] - nm1);
                S[nt][3] = exp2f(S[nt][3] - nm1);
                su0 += S[nt][0] + S[nt][1];
                su1 += S[nt][2] + S[nt][3];
            }
            su0 += __shfl_xor_sync(0xffffffffu, su0, 1);
            su0 += __shfl_xor_sync(0xffffffffu, su0, 2);
            su1 += __shfl_xor_sync(0xffffffffu, su1, 1);
            su1 += __shfl_xor_sync(0xffffffffu, su1, 2);
            l0 = l0 * al0 + su0;
            l1 = l1 * al1 + su1;
#pragma unroll
            for (int nt = 0; nt < 8; nt++) {
                O[nt][0] *= al0; O[nt][1] *= al0;
                O[nt][2] *= al1; O[nt][3] *= al1;
            }

            // ---- P to warp-private SMEM as packed fp16 ----
            {
                uint32_t* Pw = (uint32_t*)(smc + F_PS) + wq * PPADU;
#pragma unroll
                for (int nt = 0; nt < 8; nt++) {
                    Pw[r * PPADU + nt * 4 + c]       = packh(S[nt][0], S[nt][1]);
                    Pw[(r + 8) * PPADU + nt * 4 + c] = packh(S[nt][2], S[nt][3]);
                }
            }
            __syncwarp();

            // ---- O += P V (fp16, ldmatrix frags) ----
#pragma unroll
            for (int ks = 0; ks < 4; ks++) {
                uint32_t a4[4];
                ldmx4(a4, pwbase + (uint32_t)(rA * PPADU + 8 * ks + kqA) * 4);
#pragma unroll
                for (int j = 0; j < 4; j++) {
                    uint32_t v4[4];
                    uint32_t off = (uint32_t)(((2 * j + sB) * 8 + rB) * VPADU + 8 * ks + kqB) * 4;
                    ldmx4(v4, vsB + off);
#pragma unroll
                    for (int h2 = 0; h2 < 2; h2++)
                        mma16h(O[2 * j + h2], a4[0], a4[1], a4[2], a4[3],
                               v4[2 * h2], v4[2 * h2 + 1]);
                }
            }
        }
        __syncthreads();
    }

    // ---- normalize + write (fp16 packed) ----
    float i0 = 1.f / l0, i1 = 1.f / l1;
    int b = bh >> 4, h = bh & 15;
    int tr0 = t0 + wq + r;
#pragma unroll
    for (int nt = 0; nt < 8; nt++) {
        int col = h * 64 + nt * 8 + 2 * c;
        attnc[((size_t)(b * TT + tr0) * CC + col) >> 1] =
            packh(O[nt][0] * i0, O[nt][1] * i0);
        attnc[((size_t)(b * TT + tr0 + 8) * CC + col) >> 1] =
            packh(O[nt][2] * i1, O[nt][3] * i1);
    }
}

// ---------------- single fused transpose kernel ------------------------------
__global__ void transpose_all_kernel(
    const float* __restrict__ Wq, const float* __restrict__ Wk,
    const float* __restrict__ Wv, const float* __restrict__ Wo,
    const float* __restrict__ W1, const float* __restrict__ W2,
    __nv_bfloat16* __restrict__ wqkTH, __nv_bfloat16* __restrict__ wqkTL,
    __half* __restrict__ wvT, __half* __restrict__ woT,
    __half* __restrict__ w1T, __half* __restrict__ w2T)
{
    __shared__ float tile[32][33];
    int l = blockIdx.x;
    int x = threadIdx.x, y = threadIdx.y;

    if (l < 2048) {
        int z = l >> 6, rem = l & 63;
        int c0 = (rem & 1) * 32, r0 = (rem >> 1) * 32;
        const float* in = (z < 16) ? (Wq + (size_t)z * CC * DD)
                                   : (Wk + (size_t)(z - 16) * CC * DD);
        __nv_bfloat16* oh = wqkTH + (size_t)z * DD * CC;
        __nv_bfloat16* ol = wqkTL + (size_t)z * DD * CC;
#pragma unroll
        for (int i = 0; i < 32; i += 8)
            tile[y + i][x] = in[(size_t)(r0 + y + i) * DD + c0 + x];
        __syncthreads();
#pragma unroll
        for (int i = 0; i < 32; i += 8) {
            float vv = tile[x][y + i];
            __nv_bfloat16 hb = __float2bfloat16(vv);
            size_t o = (size_t)(c0 + y + i) * CC + r0 + x;
            oh[o] = hb;
            ol[o] = __float2bfloat16(vv - __bfloat162float(hb));
        }
        return;
    }

    l -= 2048;
    const float* in;
    __half* out;
    int R, Cc, c0, r0;
    if (l < 1024) {
        int h = l >> 6, rem = l & 63;
        in = Wv + (size_t)h * CC * DD;
        out = wvT + (size_t)h * DD * CC;
        R = CC; Cc = DD;
        c0 = (rem & 1) * 32; r0 = (rem >> 1) * 32;
    } else if (l < 2048) {
        int rem = l - 1024;
        in = Wo; out = woT; R = CC; Cc = CC;
        c0 = (rem & 31) * 32; r0 = (rem >> 5) * 32;
    } else if (l < 6144) {
        int rem = l - 2048;
        in = W1; out = w1T; R = CC; Cc = FFD;
        c0 = (rem & 127) * 32; r0 = (rem >> 7) * 32;
    } else {
        int rem = l - 6144;
        in = W2; out = w2T; R = FFD; Cc = CC;
        c0 = (rem & 31) * 32; r0 = (rem >> 5) * 32;
    }
#pragma unroll
    for (int i = 0; i < 32; i += 8)
        tile[y + i][x] = in[(size_t)(r0 + y + i) * Cc + c0 + x];
    __syncthreads();
#pragma unroll
    for (int i = 0; i < 32; i += 8)
        out[(size_t)(c0 + y + i) * R + r0 + x] = __float2half(tile[x][y + i]);
}

// ---------------- block reduction + LayerNorm --------------------------------
__device__ __forceinline__ float blockSumf(float v, float* red) {
    int lane = threadIdx.x & 31, w = threadIdx.x >> 5, nw = blockDim.x >> 5;
    __syncthreads();
#pragma unroll
    for (int o = 16; o > 0; o >>= 1) v += __shfl_xor_sync(0xffffffffu, v, o);
    if (lane == 0) red[w] = v;
    __syncthreads();
    if (w == 0) {
        float t = (lane < nw) ? red[lane] : 0.f;
#pragma unroll
        for (int o = 16; o > 0; o >>= 1) t += __shfl_xor_sync(0xffffffffu, t, o);
        if (lane == 0) red[0] = t;
    }
    __syncthreads();
    return red[0];
}

// MODE 0: fp16 packed out only; MODE 1: fp16 + bf16 hi/lo out
template <int MODE>
__global__ void __launch_bounds__(256) ln_kernel(
    const float* __restrict__ x, const float* __restrict__ g,
    const float* __restrict__ be, uint32_t* __restrict__ outP,
    uint32_t* __restrict__ outH, uint32_t* __restrict__ outL)
{
    __shared__ float red[8];
    size_t row = blockIdx.x;
    const float2* xr = (const float2*)(x + row * CC);
    float2 v[2];
    float s = 0.f, s2 = 0.f;
#pragma unroll
    for (int i = 0; i < 2; i++) {
        int p = threadIdx.x + i * 256;
        v[i] = xr[p];
        s += v[i].x + v[i].y;
        s2 += v[i].x * v[i].x + v[i].y * v[i].y;
    }
    s  = blockSumf(s, red);
    s2 = blockSumf(s2, red);
    float mu  = s * (1.f / CC);
    float var = s2 * (1.f / CC) - mu * mu;
    float rstd = rsqrtf(var + 1e-5f);
#pragma unroll
    for (int i = 0; i < 2; i++) {
        int p = threadIdx.x + i * 256;
        float2 gg = ((const float2*)g)[p];
        float2 bb = ((const float2*)be)[p];
        float a0 = (v[i].x - mu) * rstd * gg.x + bb.x;
        float a1 = (v[i].y - mu) * rstd * gg.y + bb.y;
        outP[row * (CC / 2) + p] = packh(a0, a1);
        if (MODE == 1) {
            uint32_t hp, lp;
            splitbf(a0, a1, hp, lp);
            outH[row * (CC / 2) + p] = hp;
            outL[row * (CC / 2) + p] = lp;
        }
    }
}

// ---------------- launch ----------------------------------------------------
extern "C" void kernel_launch(void* const* d_in, const int* in_sizes, int n_in,
                              void* d_out, int out_size)
{
    const float* x   = (const float*)d_in[0];
    const float* Wq  = (const float*)d_in[1];
    const float* Wk  = (const float*)d_in[2];
    const float* Wv  = (const float*)d_in[3];
    const float* Wo  = (const float*)d_in[4];
    const float* bo  = (const float*)d_in[5];
    const float* W1  = (const float*)d_in[6];
    const float* b1  = (const float*)d_in[7];
    const float* W2  = (const float*)d_in[8];
    const float* b2  = (const float*)d_in[9];
    const float* g1  = (const float*)d_in[10];
    const float* be1 = (const float*)d_in[11];
    const float* g2  = (const float*)d_in[12];
    const float* be2 = (const float*)d_in[13];
    float* out = (float*)d_out;

    uint32_t *ln16, *lnH2, *lnH, *lnL, *qH, *qL, *attnc, *ff1;
    __nv_bfloat16 *kH, *kL, *wqkTH, *wqkTL;
    __half *vT, *wvT, *woT, *w1T, *w2T;
    float *x1;
    cudaGetSymbolAddress((void**)&ln16,  g_ln16);
    cudaGetSymbolAddress((void**)&lnH2,  g_lnH2);
    cudaGetSymbolAddress((void**)&lnH,   g_lnH);
    cudaGetSymbolAddress((void**)&lnL,   g_lnL);
    cudaGetSymbolAddress((void**)&qH,    g_qH);
    cudaGetSymbolAddress((void**)&qL,    g_qL);
    cudaGetSymbolAddress((void**)&kH,    g_kH);
    cudaGetSymbolAddress((void**)&kL,    g_kL);
    cudaGetSymbolAddress((void**)&vT,    g_vT);
    cudaGetSymbolAddress((void**)&attnc, g_attnc);
    cudaGetSymbolAddress((void**)&x1,    g_x1);
    cudaGetSymbolAddress((void**)&ff1,   g_ff1);
    cudaGetSymbolAddress((void**)&wqkTH, g_wqkTH);
    cudaGetSymbolAddress((void**)&wqkTL, g_wqkTL);
    cudaGetSymbolAddress((void**)&wvT,   g_wvT);
    cudaGetSymbolAddress((void**)&woT,   g_woT);
    cudaGetSymbolAddress((void**)&w1T,   g_w1T);
    cudaGetSymbolAddress((void**)&w2T,   g_w2T);

    cudaFuncSetAttribute(qk_gemm, cudaFuncAttributeMaxDynamicSharedMemorySize, QSMEM_BYTES);
    cudaFuncSetAttribute(hgemm<1024,1024,1>, cudaFuncAttributeMaxDynamicSharedMemorySize, HSMEM_BYTES);
    cudaFuncSetAttribute(hgemm<1024,1024,3>, cudaFuncAttributeMaxDynamicSharedMemorySize, HSMEM_BYTES);
    cudaFuncSetAttribute(hgemm<4096,1024,2>, cudaFuncAttributeMaxDynamicSharedMemorySize, HSMEM_BYTES);
    cudaFuncSetAttribute(hgemm<1024,4096,1>, cudaFuncAttributeMaxDynamicSharedMemorySize, HSMEM_BYTES);
    cudaFuncSetAttribute(flash_kernel, cudaFuncAttributeMaxDynamicSharedMemorySize, FSMEM_BYTES);

    dim3 tb(32, 8);
    // 0. LN1 -> fp16 + bf16 hi/lo
    ln_kernel<1><<<NTOK, 256>>>(x, g1, be1, ln16, lnH, lnL);
    // 1. all weight transposes (one launch)
    transpose_all_kernel<<<12288, tb>>>(Wq, Wk, Wv, Wo, W1, W2,
                                        wqkTH, wqkTL, wvT, woT, w1T, w2T);
    // 2. Q,K projection (bf16x3); Q pre-scaled by log2e
    qk_gemm<<<dim3(16, 64), 512, QSMEM_BYTES>>>(
        (__nv_bfloat16*)lnH, (__nv_bfloat16*)lnL, wqkTH, wqkTL, qH, qL,
        (uint32_t*)kH, (uint32_t*)kL);
    // 3. V projection (fp16 single) -> V^T fp16
    hgemm<1024,1024,3><<<dim3(8, 64), 512, HSMEM_BYTES>>>(
        ln16, (const uint32_t*)wvT, vT, nullptr, nullptr);
    // 4. flash attention -> concat heads (fp16)
    flash_kernel<<<dim3(16, 64), 256, FSMEM_BYTES>>>(qH, qL, kH, kL, (uint32_t*)vT, attnc);
    // 5. x1 = x + attnc @ Wo + bo
    hgemm<1024,1024,1><<<dim3(8, 64), 512, HSMEM_BYTES>>>(
        attnc, (const uint32_t*)woT, x1, bo, x);
    // 6. LN2 -> fp16
    ln_kernel<0><<<NTOK, 256>>>(x1, g2, be2, lnH2, nullptr, nullptr);
    // 7. ff1 = relu(ln2 @ W1 + b1)
    hgemm<4096,1024,2><<<dim3(32, 64), 512, HSMEM_BYTES>>>(
        lnH2, (const uint32_t*)w1T, ff1, b1, nullptr);
    // 8. out = x1 + ff1 @ W2 + b2
    hgemm<1024,4096,1><<<dim3(8, 64), 512, HSMEM_BYTES>>>(
        ff1, (const uint32_t*)w2T, out, b2, x1);
}

// round 17
// speedup vs baseline: 1.0119x; 1.0119x over previous
#include <cuda_runtime.h>
#include <cuda_fp16.h>
#include <cuda_bf16.h>
#include <cstdint>

// Problem constants
#define BB 4
#define TT 2048
#define CC 1024
#define HH 16
#define DD 64
#define FFD 4096
#define NTOK (BB*TT)          // 8192
#define LOG2E 1.4426950408889634f

// ---------------- scratch (device globals; no allocation allowed) -----------
__device__ uint32_t g_ln16 [NTOK * CC / 2];          // LN1 out, fp16 pairs
__device__ uint32_t g_lnH2 [NTOK * CC / 2];          // LN2 out, fp16 pairs
__device__ uint32_t g_lnH  [NTOK * CC / 2];          // LN1 out, bf16 hi pairs
__device__ uint32_t g_lnL  [NTOK * CC / 2];          // LN1 out, bf16 lo pairs
__device__ uint32_t g_qH   [BB*HH * TT * DD / 2];    // Q bf16 hi pairs (x log2e)
__device__ uint32_t g_qL   [BB*HH * TT * DD / 2];
__device__ __nv_bfloat16 g_kH [BB*HH * TT * DD];
__device__ __nv_bfloat16 g_kL [BB*HH * TT * DD];
__device__ __half   g_vT   [BB*HH * DD * TT];        // V fp16 TRANSPOSED [bh][d][t]
__device__ uint32_t g_attnc[NTOK * CC / 2];          // fp16 pairs
__device__ float    g_x1   [NTOK * CC];
__device__ uint32_t g_ff1  [NTOK * FFD / 2];         // fp16 pairs
__device__ __nv_bfloat16 g_wqkTH[2*CC * CC];         // Wq^T,Wk^T bf16 hi
__device__ __nv_bfloat16 g_wqkTL[2*CC * CC];
__device__ __half   g_wvT  [CC * CC];                // Wv^T fp16
__device__ __half   g_woT  [CC * CC];
__device__ __half   g_w1T  [FFD * CC];
__device__ __half   g_w2T  [CC * FFD];

// ---------------- low-level helpers -----------------------------------------
__device__ __forceinline__ uint32_t smem_u32(const void* p) {
    uint32_t a;
    asm("{ .reg .u64 t; cvta.to.shared.u64 t, %1; cvt.u32.u64 %0, t; }"
        : "=r"(a) : "l"(p));
    return a;
}
__device__ __forceinline__ void cp16(uint32_t s, const void* g) {
    asm volatile("cp.async.cg.shared.global [%0], [%1], 16;" :: "r"(s), "l"(g));
}
__device__ __forceinline__ void cpcommit() {
    asm volatile("cp.async.commit_group;" ::: "memory");
}
template <int N>
__device__ __forceinline__ void cpwait() {
    asm volatile("cp.async.wait_group %0;" :: "n"(N) : "memory");
}
__device__ __forceinline__ void ldmx4(uint32_t* r, uint32_t addr) {
    asm volatile(
        "ldmatrix.sync.aligned.m8n8.x4.shared.b16 {%0,%1,%2,%3}, [%4];"
        : "=r"(r[0]), "=r"(r[1]), "=r"(r[2]), "=r"(r[3]) : "r"(addr));
}
__device__ __forceinline__ void mma16b(float* d, uint32_t a0, uint32_t a1,
                                       uint32_t a2, uint32_t a3,
                                       uint32_t b0, uint32_t b1) {
    asm volatile(
        "mma.sync.aligned.m16n8k16.row.col.f32.bf16.bf16.f32 "
        "{%0,%1,%2,%3}, {%4,%5,%6,%7}, {%8,%9}, {%0,%1,%2,%3};"
        : "+f"(d[0]), "+f"(d[1]), "+f"(d[2]), "+f"(d[3])
        : "r"(a0), "r"(a1), "r"(a2), "r"(a3), "r"(b0), "r"(b1));
}
__device__ __forceinline__ void mma16h(float* d, uint32_t a0, uint32_t a1,
                                       uint32_t a2, uint32_t a3,
                                       uint32_t b0, uint32_t b1) {
    asm volatile(
        "mma.sync.aligned.m16n8k16.row.col.f32.f16.f16.f32 "
        "{%0,%1,%2,%3}, {%4,%5,%6,%7}, {%8,%9}, {%0,%1,%2,%3};"
        : "+f"(d[0]), "+f"(d[1]), "+f"(d[2]), "+f"(d[3])
        : "r"(a0), "r"(a1), "r"(a2), "r"(a3), "r"(b0), "r"(b1));
}
__device__ __forceinline__ uint32_t packbf(float x, float y) {
    __nv_bfloat162 t = __floats2bfloat162_rn(x, y);
    return *reinterpret_cast<uint32_t*>(&t);
}
__device__ __forceinline__ uint32_t packh(float x, float y) {
    __half2 t = __floats2half2_rn(x, y);
    return *reinterpret_cast<uint32_t*>(&t);
}
__device__ __forceinline__ void splitbf(float x, float y, uint32_t& hp, uint32_t& lp) {
    float hx = __bfloat162float(__float2bfloat16(x));
    float hy = __bfloat162float(__float2bfloat16(y));
    hp = packbf(hx, hy);
    lp = packbf(x - hx, y - hy);
}

// ================= QK GEMM: bf16x3, 512 threads, warp tile 32x32 =============
#define QST 4
#define QPADU 20
#define QTILEU (128*QPADU)
#define QSMEM_BYTES (4*QST*QTILEU*4)       // 163840

__global__ void __launch_bounds__(512, 1) qk_gemm(
    const __nv_bfloat16* __restrict__ AH, const __nv_bfloat16* __restrict__ AL,
    const __nv_bfloat16* __restrict__ BH, const __nv_bfloat16* __restrict__ BL,
    uint32_t* __restrict__ qHo, uint32_t* __restrict__ qLo,
    uint32_t* __restrict__ kHo, uint32_t* __restrict__ kLo)
{
    extern __shared__ uint32_t smq[];
    uint32_t aH = smem_u32(smq);
    uint32_t aL = aH + QST * QTILEU * 4;
    uint32_t bH = aH + 2 * QST * QTILEU * 4;
    uint32_t bL = aH + 3 * QST * QTILEU * 4;
    int tid = threadIdx.x, wid = tid >> 5, lane = tid & 31;
    int r = lane >> 2, c = lane & 3;
    int wm = (wid & 3) * 32, wn = (wid >> 2) * 32;
    int row0 = blockIdx.y * 128, col0 = blockIdx.x * 128;

    int rA  = (lane & 7) + ((lane >> 3) & 1) * 8;
    int kqA = (lane >> 4) * 4;
    int rB  = (lane & 7);
    int sB  = (lane >> 4);
    int kqB = ((lane >> 3) & 1) * 4;

    auto loadst = [&](int slot, int kt) {
        int k0 = kt * 32;
        int row = tid >> 2, ch = tid & 3;
        uint32_t doff = (uint32_t)(slot * QTILEU + row * QPADU + ch * 4) * 4;
        size_t sa = (size_t)(row0 + row) * CC + k0 + ch * 8;
        size_t sb = (size_t)(col0 + row) * CC + k0 + ch * 8;
        cp16(aH + doff, AH + sa);
        cp16(aL + doff, AL + sa);
        cp16(bH + doff, BH + sb);
        cp16(bL + doff, BL + sb);
    };

    float acc[2][4][4] = {};
    loadst(0, 0); cpcommit();
    loadst(1, 1); cpcommit();

    for (int kt = 0; kt < 32; kt++) {
        if (kt + 2 < 32) loadst((kt + 2) & 3, kt + 2);
        cpcommit();
        cpwait<2>();
        __syncthreads();
        uint32_t stoff = (uint32_t)((kt & 3) * QTILEU) * 4;
#pragma unroll
        for (int s = 0; s < 2; s++) {
            int pb = s * 8;
            uint32_t ah[2][4], al[2][4], bhp[2][4], blp[2][4];
#pragma unroll
            for (int mt = 0; mt < 2; mt++) {
                uint32_t off = (uint32_t)((wm + mt * 16 + rA) * QPADU + pb + kqA) * 4;
                ldmx4(ah[mt], aH + stoff + off);
                ldmx4(al[mt], aL + stoff + off);
            }
#pragma unroll
            for (int j = 0; j < 2; j++) {
                uint32_t off = (uint32_t)((wn + (2 * j + sB) * 8 + rB) * QPADU + pb + kqB) * 4;
                ldmx4(bhp[j], bH + stoff + off);
                ldmx4(blp[j], bL + stoff + off);
            }
#pragma unroll
            for (int mt = 0; mt < 2; mt++)
#pragma unroll
                for (int j = 0; j < 2; j++)
#pragma unroll
                    for (int h2 = 0; h2 < 2; h2++) {
                        float* a4 = acc[mt][2 * j + h2];
                        uint32_t b0 = bhp[j][2 * h2], b1 = bhp[j][2 * h2 + 1];
                        mma16b(a4, ah[mt][0], ah[mt][1], ah[mt][2], ah[mt][3], b0, b1);
                        mma16b(a4, al[mt][0], al[mt][1], al[mt][2], al[mt][3], b0, b1);
                        mma16b(a4, ah[mt][0], ah[mt][1], ah[mt][2], ah[mt][3],
                               blp[j][2 * h2], blp[j][2 * h2 + 1]);
                    }
        }
    }

    // epilogue: scatter q (bf16 H/L, pre-scaled by log2e), k (bf16 H/L)
#pragma unroll
    for (int mt = 0; mt < 2; mt++) {
        int rg0 = row0 + wm + mt * 16 + r;
#pragma unroll
        for (int nt = 0; nt < 4; nt++) {
            int cg = col0 + wn + nt * 8 + 2 * c;
            int sel = cg >> 10;
            int h = (cg >> 6) & 15;
            int d = cg & 63;
            uint32_t* H = sel ? kHo : qHo;
            uint32_t* L = sel ? kLo : qLo;
            float scale = sel ? 1.f : LOG2E;
#pragma unroll
            for (int half_ = 0; half_ < 2; half_++) {
                int rg = rg0 + half_ * 8;
                int bb = rg >> 11, t = rg & 2047;
                size_t ofs = (((size_t)(bb * HH + h) * TT + t) << 6) + d;
                uint32_t hp, lp;
                splitbf(acc[mt][nt][half_ * 2 + 0] * scale,
                        acc[mt][nt][half_ * 2 + 1] * scale, hp, lp);
                H[ofs >> 1] = hp;
                L[ofs >> 1] = lp;
            }
        }
    }
}

// ================= fp16 GEMM (V-proj, Wo, W1, W2), 512 threads ===============
// Stage count ST is per-shape: 5 (prefetch 3) for small latency-bound GEMMs,
// 4 (prefetch 2) for the large throughput-bound ones.
#define HPADU 20
#define HTILEU (128*HPADU)
#define HSMEM(ST) (2*(ST)*HTILEU*4)

template <int NN, int KK, int EPI, int ST>
__global__ void __launch_bounds__(512, 1) hgemm(
    const uint32_t* __restrict__ A, const uint32_t* __restrict__ BT,
    void* __restrict__ Op,
    const float* __restrict__ bias, const float* __restrict__ res)
{
    extern __shared__ uint32_t smh[];
    uint32_t aS = smem_u32(smh);
    uint32_t bS = aS + ST * HTILEU * 4;
    int tid = threadIdx.x, wid = tid >> 5, lane = tid & 31;
    int r = lane >> 2, c = lane & 3;
    int wm = (wid & 3) * 32, wn = (wid >> 2) * 32;
    int row0 = blockIdx.y * 128, col0 = blockIdx.x * 128;
    constexpr int KU = KK / 2;
    constexpr int PF = ST - 2;             // prefetch distance
    const uint32_t* Ag = A + (size_t)row0 * KU;
    const uint32_t* Bg = BT + (size_t)col0 * KU;

    int rA  = (lane & 7) + ((lane >> 3) & 1) * 8;
    int kqA = (lane >> 4) * 4;
    int rB  = (lane & 7);
    int sB  = (lane >> 4);
    int kqB = ((lane >> 3) & 1) * 4;

    auto loadst = [&](int slot, int kt) {
        int k0 = kt * 16;
        int row = tid >> 2, ch = tid & 3;
        uint32_t doff = (uint32_t)(slot * HTILEU + row * HPADU + ch * 4) * 4;
        cp16(aS + doff, Ag + (size_t)row * KU + k0 + ch * 4);
        cp16(bS + doff, Bg + (size_t)row * KU + k0 + ch * 4);
    };

    float acc[2][4][4] = {};
    constexpr int KT = KK / 32;
#pragma unroll
    for (int p = 0; p < PF; p++) { loadst(p, p); cpcommit(); }

    for (int kt = 0; kt < KT; kt++) {
        if (kt + PF < KT) loadst((kt + PF) % ST, kt + PF);
        cpcommit();
        cpwait<PF>();
        __syncthreads();     // write stages (kt+PF)%ST / skew-1 (kt+PF+1)%ST
                             // never alias read stage kt%ST (PF+1 < ST... PF+1<=ST-1) OK
        uint32_t stoff = (uint32_t)((kt % ST) * HTILEU) * 4;
#pragma unroll
        for (int s = 0; s < 2; s++) {
            int pb = s * 8;
            uint32_t a[2][4], bp[2][4];
#pragma unroll
            for (int mt = 0; mt < 2; mt++) {
                uint32_t off = (uint32_t)((wm + mt * 16 + rA) * HPADU + pb + kqA) * 4;
                ldmx4(a[mt], aS + stoff + off);
            }
#pragma unroll
            for (int j = 0; j < 2; j++) {
                uint32_t off = (uint32_t)((wn + (2 * j + sB) * 8 + rB) * HPADU + pb + kqB) * 4;
                ldmx4(bp[j], bS + stoff + off);
            }
#pragma unroll
            for (int mt = 0; mt < 2; mt++)
#pragma unroll
                for (int j = 0; j < 2; j++)
#pragma unroll
                    for (int h2 = 0; h2 < 2; h2++)
                        mma16h(acc[mt][2 * j + h2], a[mt][0], a[mt][1], a[mt][2],
                               a[mt][3], bp[j][2 * h2], bp[j][2 * h2 + 1]);
        }
    }

#pragma unroll
    for (int mt = 0; mt < 2; mt++) {
        int rg0 = row0 + wm + mt * 16 + r;
#pragma unroll
        for (int nt = 0; nt < 4; nt++) {
            int cg = col0 + wn + nt * 8 + 2 * c;
#pragma unroll
            for (int half_ = 0; half_ < 2; half_++) {
                int rg = rg0 + half_ * 8;
                float v0 = acc[mt][nt][half_ * 2 + 0];
                float v1 = acc[mt][nt][half_ * 2 + 1];
                if (EPI == 3) {
                    int h = cg >> 6, d = cg & 63;
                    int bb = rg >> 11, t = rg & 2047;
                    __half* vp = (__half*)Op +
                        ((size_t)(bb * HH + h) * DD + d) * TT + t;
                    vp[0]  = __float2half(v0);
                    vp[TT] = __float2half(v1);
                } else {
                    size_t off = (size_t)rg * NN + cg;
                    float2 b2 = *(const float2*)(bias + cg);
                    if (EPI == 1) {
                        float2 r2 = *(const float2*)(res + off);
                        *(float2*)((float*)Op + off) =
                            make_float2(v0 + b2.x + r2.x, v1 + b2.y + r2.y);
                    } else {
                        ((uint32_t*)Op)[off >> 1] =
                            packh(fmaxf(v0 + b2.x, 0.f), fmaxf(v1 + b2.y, 0.f));
                    }
                }
            }
        }
    }
}

// ================= flash attention: bf16x3 QK^T (log2 domain), fp16 PV =======
#define KPADU 36
#define VPADU 36
#define PPADU 36
#define QPADF 36
#define F_KH 0
#define F_KL 18432
#define F_V  36864
#define F_QH 55296
#define F_QL 73728
#define F_PS 92160
#define FSMEM_BYTES 110592

__global__ void __launch_bounds__(256, 2) flash_kernel(
    const uint32_t* __restrict__ qH, const uint32_t* __restrict__ qL,
    const __nv_bfloat16* __restrict__ kH, const __nv_bfloat16* __restrict__ kL,
    const uint32_t* __restrict__ vT, uint32_t* __restrict__ attnc)
{
    extern __shared__ char smc[];
    uint32_t base = smem_u32(smc);

    int tid = threadIdx.x, wid = tid >> 5, lane = tid & 31;
    int r = lane >> 2, c = lane & 3;
    int qt = (int)gridDim.x - 1 - (int)blockIdx.x;   // longest blocks first
    int bh = blockIdx.y;
    int t0 = qt * 128;
    int wq = wid * 16;
    const uint32_t* qH32 = qH + (size_t)bh * TT * 32;
    const uint32_t* qL32 = qL + (size_t)bh * TT * 32;
    const __nv_bfloat16* kHb = kH + (size_t)bh * TT * DD;
    const __nv_bfloat16* kLb = kL + (size_t)bh * TT * DD;
    const uint32_t* vT32 = vT + (size_t)bh * DD * (TT / 2);

    int rA  = (lane & 7) + ((lane >> 3) & 1) * 8;
    int kqA = (lane >> 4) * 4;
    int rB  = (lane & 7);
    int sB  = (lane >> 4);
    int kqB = ((lane >> 3) & 1) * 4;

    // stage Q tile (hi/lo) into SMEM via cp.async (rides first commit group)
    {
        uint32_t qhS = base + F_QH, qlS = base + F_QL;
#pragma unroll
        for (int i = 0; i < 4; i++) {
            int j = tid + i * 256;
            int row = j >> 3, ch = j & 7;
            uint32_t doff = (uint32_t)(row * QPADF + ch * 4) * 4;
            size_t src = (size_t)(t0 + row) * 32 + ch * 4;
            cp16(qhS + doff, qH32 + src);
            cp16(qlS + doff, qL32 + src);
        }
    }

    auto loadkv = [&](int buf, int it) {
        int s0 = it * 64;
        uint32_t kh = base + F_KH + buf * 9216;
        uint32_t kl = base + F_KL + buf * 9216;
        uint32_t vs = base + F_V + buf * 9216;
#pragma unroll
        for (int i = 0; i < 2; i++) {
            int j = tid + i * 256;
            int row = j >> 3, ch = j & 7;
            uint32_t doff = (uint32_t)(row * KPADU + ch * 4) * 4;
            size_t src = (size_t)(s0 + row) * DD + ch * 8;
            cp16(kh + doff, kHb + src);
            cp16(kl + doff, kLb + src);
        }
#pragma unroll
        for (int i = 0; i < 2; i++) {
            int j = tid + i * 256;
            int row = j >> 3, ch = j & 7;
            cp16(vs + (uint32_t)(row * VPADU + ch * 4) * 4,
                 vT32 + (size_t)row * (TT / 2) + (s0 >> 1) + ch * 4);
        }
    };

    int nst = 2 * qt + 2;
    loadkv(0, 0); cpcommit();

    float m0 = -1e30f, m1 = -1e30f, l0 = 0.f, l1 = 0.f;
    float O[8][4] = {};
    uint32_t pwbase = base + F_PS + (uint32_t)(wq * PPADU) * 4;
    uint32_t qhW = base + F_QH + (uint32_t)(wq * QPADF) * 4;
    uint32_t qlW = base + F_QL + (uint32_t)(wq * QPADF) * 4;

    for (int it = 0; it < nst; it++) {
        if (it + 1 < nst) loadkv((it + 1) & 1, it + 1);
        cpcommit();
        cpwait<1>();
        __syncthreads();
        int s0 = it * 64;
        if (s0 <= t0 + wq + 15) {
            uint32_t khB = base + F_KH + (it & 1) * 9216;
            uint32_t klB = base + F_KL + (it & 1) * 9216;
            uint32_t vsB = base + F_V + (it & 1) * 9216;

            // ---- S = Q K^T (bf16x3, log2 domain) ----
            float S[8][4] = {};
#pragma unroll
            for (int s = 0; s < 4; s++) {
                uint32_t qh4[4], ql4[4];
                uint32_t qoff = (uint32_t)(rA * QPADF + s * 8 + kqA) * 4;
                ldmx4(qh4, qhW + qoff);
                ldmx4(ql4, qlW + qoff);
#pragma unroll
                for (int j = 0; j < 4; j++) {
                    uint32_t off = (uint32_t)(((2 * j + sB) * 8 + rB) * KPADU + s * 8 + kqB) * 4;
                    uint32_t bh4[4], bl4[4];
                    ldmx4(bh4, khB + off);
                    ldmx4(bl4, klB + off);
#pragma unroll
                    for (int h2 = 0; h2 < 2; h2++) {
                        float* s4 = S[2 * j + h2];
                        uint32_t b0 = bh4[2 * h2], b1 = bh4[2 * h2 + 1];
                        mma16b(s4, qh4[0], qh4[1], qh4[2], qh4[3], b0, b1);
                        mma16b(s4, ql4[0], ql4[1], ql4[2], ql4[3], b0, b1);
                        mma16b(s4, qh4[0], qh4[1], qh4[2], qh4[3],
                               bl4[2 * h2], bl4[2 * h2 + 1]);
                    }
                }
            }

            // ---- causal mask ----
            if (s0 + 63 > t0 + wq) {
#pragma unroll
                for (int nt = 0; nt < 8; nt++)
#pragma unroll
                    for (int jj = 0; jj < 4; jj++) {
                        int scol = s0 + nt * 8 + 2 * c + (jj & 1);
                        int trow = t0 + wq + r + ((jj >> 1) << 3);
                        if (scol > trow) S[nt][jj] = -1e30f;
                    }
            }

            // ---- online softmax (log2 domain) ----
            float mx0 = -1e30f, mx1 = -1e30f;
#pragma unroll
            for (int nt = 0; nt < 8; nt++) {
                mx0 = fmaxf(mx0, fmaxf(S[nt][0], S[nt][1]));
                mx1 = fmaxf(mx1, fmaxf(S[nt][2], S[nt][3]));
            }
            mx0 = fmaxf(mx0, __shfl_xor_sync(0xffffffffu, mx0, 1));
            mx0 = fmaxf(mx0, __shfl_xor_sync(0xffffffffu, mx0, 2));
            mx1 = fmaxf(mx1, __shfl_xor_sync(0xffffffffu, mx1, 1));
            mx1 = fmaxf(mx1, __shfl_xor_sync(0xffffffffu, mx1, 2));
            float nm0 = fmaxf(m0, mx0), nm1 = fmaxf(m1, mx1);
            float al0 = exp2f(m0 - nm0), al1 = exp2f(m1 - nm1);
            m0 = nm0; m1 = nm1;
            float su0 = 0.f, su1 = 0.f;
#pragma unroll
            for (int nt = 0; nt < 8; nt++) {
                S[nt][0] = exp2f(S[nt][0] - nm0);
                S[nt][1] = exp2f(S[nt][1] - nm0);
                S[nt][2] = exp2f(S[nt][2] - nm1);
                S[nt][3] = exp2f(S[nt][3] - nm1);
                su0 += S[nt][0] + S[nt][1];
                su1 += S[nt][2] + S[nt][3];
            }
            su0 += __shfl_xor_sync(0xffffffffu, su0, 1);
            su0 += __shfl_xor_sync(0xffffffffu, su0, 2);
            su1 += __shfl_xor_sync(0xffffffffu, su1, 1);
            su1 += __shfl_xor_sync(0xffffffffu, su1, 2);
            l0 = l0 * al0 + su0;
            l1 = l1 * al1 + su1;
#pragma unroll
            for (int nt = 0; nt < 8; nt++) {
                O[nt][0] *= al0; O[nt][1] *= al0;
                O[nt][2] *= al1; O[nt][3] *= al1;
            }

            // ---- P to warp-private SMEM as packed fp16 ----
            {
                uint32_t* Pw = (uint32_t*)(smc + F_PS) + wq * PPADU;
#pragma unroll
                for (int nt = 0; nt < 8; nt++) {
                    Pw[r * PPADU + nt * 4 + c]       = packh(S[nt][0], S[nt][1]);
                    Pw[(r + 8) * PPADU + nt * 4 + c] = packh(S[nt][2], S[nt][3]);
                }
            }
            __syncwarp();

            // ---- O += P V (fp16, ldmatrix frags) ----
#pragma unroll
            for (int ks = 0; ks < 4; ks++) {
                uint32_t a4[4];
                ldmx4(a4, pwbase + (uint32_t)(rA * PPADU + 8 * ks + kqA) * 4);
#pragma unroll
                for (int j = 0; j < 4; j++) {
                    uint32_t v4[4];
                    uint32_t off = (uint32_t)(((2 * j + sB) * 8 + rB) * VPADU + 8 * ks + kqB) * 4;
                    ldmx4(v4, vsB + off);
#pragma unroll
                    for (int h2 = 0; h2 < 2; h2++)
                        mma16h(O[2 * j + h2], a4[0], a4[1], a4[2], a4[3],
                               v4[2 * h2], v4[2 * h2 + 1]);
                }
            }
        }
        __syncthreads();
    }

    // ---- normalize + write (fp16 packed) ----
    float i0 = 1.f / l0, i1 = 1.f / l1;
    int b = bh >> 4, h = bh & 15;
    int tr0 = t0 + wq + r;
#pragma unroll
    for (int nt = 0; nt < 8; nt++) {
        int col = h * 64 + nt * 8 + 2 * c;
        attnc[((size_t)(b * TT + tr0) * CC + col) >> 1] =
            packh(O[nt][0] * i0, O[nt][1] * i0);
        attnc[((size_t)(b * TT + tr0 + 8) * CC + col) >> 1] =
            packh(O[nt][2] * i1, O[nt][3] * i1);
    }
}

// ---------------- single fused transpose kernel ------------------------------
__global__ void transpose_all_kernel(
    const float* __restrict__ Wq, const float* __restrict__ Wk,
    const float* __restrict__ Wv, const float* __restrict__ Wo,
    const float* __restrict__ W1, const float* __restrict__ W2,
    __nv_bfloat16* __restrict__ wqkTH, __nv_bfloat16* __restrict__ wqkTL,
    __half* __restrict__ wvT, __half* __restrict__ woT,
    __half* __restrict__ w1T, __half* __restrict__ w2T)
{
    __shared__ float tile[32][33];
    int l = blockIdx.x;
    int x = threadIdx.x, y = threadIdx.y;

    if (l < 2048) {
        int z = l >> 6, rem = l & 63;
        int c0 = (rem & 1) * 32, r0 = (rem >> 1) * 32;
        const float* in = (z < 16) ? (Wq + (size_t)z * CC * DD)
                                   : (Wk + (size_t)(z - 16) * CC * DD);
        __nv_bfloat16* oh = wqkTH + (size_t)z * DD * CC;
        __nv_bfloat16* ol = wqkTL + (size_t)z * DD * CC;
#pragma unroll
        for (int i = 0; i < 32; i += 8)
            tile[y + i][x] = in[(size_t)(r0 + y + i) * DD + c0 + x];
        __syncthreads();
#pragma unroll
        for (int i = 0; i < 32; i += 8) {
            float vv = tile[x][y + i];
            __nv_bfloat16 hb = __float2bfloat16(vv);
            size_t o = (size_t)(c0 + y + i) * CC + r0 + x;
            oh[o] = hb;
            ol[o] = __float2bfloat16(vv - __bfloat162float(hb));
        }
        return;
    }

    l -= 2048;
    const float* in;
    __half* out;
    int R, Cc, c0, r0;
    if (l < 1024) {
        int h = l >> 6, rem = l & 63;
        in = Wv + (size_t)h * CC * DD;
        out = wvT + (size_t)h * DD * CC;
        R = CC; Cc = DD;
        c0 = (rem & 1) * 32; r0 = (rem >> 1) * 32;
    } else if (l < 2048) {
        int rem = l - 1024;
        in = Wo; out = woT; R = CC; Cc = CC;
        c0 = (rem & 31) * 32; r0 = (rem >> 5) * 32;
    } else if (l < 6144) {
        int rem = l - 2048;
        in = W1; out = w1T; R = CC; Cc = FFD;
        c0 = (rem & 127) * 32; r0 = (rem >> 7) * 32;
    } else {
        int rem = l - 6144;
        in = W2; out = w2T; R = FFD; Cc = CC;
        c0 = (rem & 31) * 32; r0 = (rem >> 5) * 32;
    }
#pragma unroll
    for (int i = 0; i < 32; i += 8)
        tile[y + i][x] = in[(size_t)(r0 + y + i) * Cc + c0 + x];
    __syncthreads();
#pragma unroll
    for (int i = 0; i < 32; i += 8)
        out[(size_t)(c0 + y + i) * R + r0 + x] = __float2half(tile[x][y + i]);
}

// ---------------- block reduction + LayerNorm --------------------------------
__device__ __forceinline__ float blockSumf(float v, float* red) {
    int lane = threadIdx.x & 31, w = threadIdx.x >> 5, nw = blockDim.x >> 5;
    __syncthreads();
#pragma unroll
    for (int o = 16; o > 0; o >>= 1) v += __shfl_xor_sync(0xffffffffu, v, o);
    if (lane == 0) red[w] = v;
    __syncthreads();
    if (w == 0) {
        float t = (lane < nw) ? red[lane] : 0.f;
#pragma unroll
        for (int o = 16; o > 0; o >>= 1) t += __shfl_xor_sync(0xffffffffu, t, o);
        if (lane == 0) red[0] = t;
    }
    __syncthreads();
    return red[0];
}

// MODE 0: fp16 packed out only; MODE 1: fp16 + bf16 hi/lo out
template <int MODE>
__global__ void __launch_bounds__(256) ln_kernel(
    const float* __restrict__ x, const float* __restrict__ g,
    const float* __restrict__ be, uint32_t* __restrict__ outP,
    uint32_t* __restrict__ outH, uint32_t* __restrict__ outL)
{
    __shared__ float red[8];
    size_t row = blockIdx.x;
    const float2* xr = (const float2*)(x + row * CC);
    float2 v[2];
    float s = 0.f, s2 = 0.f;
#pragma unroll
    for (int i = 0; i < 2; i++) {
        int p = threadIdx.x + i * 256;
        v[i] = xr[p];
        s += v[i].x + v[i].y;
        s2 += v[i].x * v[i].x + v[i].y * v[i].y;
    }
    s  = blockSumf(s, red);
    s2 = blockSumf(s2, red);
    float mu  = s * (1.f / CC);
    float var = s2 * (1.f / CC) - mu * mu;
    float rstd = rsqrtf(var + 1e-5f);
#pragma unroll
    for (int i = 0; i < 2; i++) {
        int p = threadIdx.x + i * 256;
        float2 gg = ((const float2*)g)[p];
        float2 bb = ((const float2*)be)[p];
        float a0 = (v[i].x - mu) * rstd * gg.x + bb.x;
        float a1 = (v[i].y - mu) * rstd * gg.y + bb.y;
        outP[row * (CC / 2) + p] = packh(a0, a1);
        if (MODE == 1) {
            uint32_t hp, lp;
            splitbf(a0, a1, hp, lp);
            outH[row * (CC / 2) + p] = hp;
            outL[row * (CC / 2) + p] = lp;
        }
    }
}

// ---------------- launch ----------------------------------------------------
extern "C" void kernel_launch(void* const* d_in, const int* in_sizes, int n_in,
                              void* d_out, int out_size)
{
    const float* x   = (const float*)d_in[0];
    const float* Wq  = (const float*)d_in[1];
    const float* Wk  = (const float*)d_in[2];
    const float* Wv  = (const float*)d_in[3];
    const float* Wo  = (const float*)d_in[4];
    const float* bo  = (const float*)d_in[5];
    const float* W1  = (const float*)d_in[6];
    const float* b1  = (const float*)d_in[7];
    const float* W2  = (const float*)d_in[8];
    const float* b2  = (const float*)d_in[9];
    const float* g1  = (const float*)d_in[10];
    const float* be1 = (const float*)d_in[11];
    const float* g2  = (const float*)d_in[12];
    const float* be2 = (const float*)d_in[13];
    float* out = (float*)d_out;

    uint32_t *ln16, *lnH2, *lnH, *lnL, *qH, *qL, *attnc, *ff1;
    __nv_bfloat16 *kH, *kL, *wqkTH, *wqkTL;
    __half *vT, *wvT, *woT, *w1T, *w2T;
    float *x1;
    cudaGetSymbolAddress((void**)&ln16,  g_ln16);
    cudaGetSymbolAddress((void**)&lnH2,  g_lnH2);
    cudaGetSymbolAddress((void**)&lnH,   g_lnH);
    cudaGetSymbolAddress((void**)&lnL,   g_lnL);
    cudaGetSymbolAddress((void**)&qH,    g_qH);
    cudaGetSymbolAddress((void**)&qL,    g_qL);
    cudaGetSymbolAddress((void**)&kH,    g_kH);
    cudaGetSymbolAddress((void**)&kL,    g_kL);
    cudaGetSymbolAddress((void**)&vT,    g_vT);
    cudaGetSymbolAddress((void**)&attnc, g_attnc);
    cudaGetSymbolAddress((void**)&x1,    g_x1);
    cudaGetSymbolAddress((void**)&ff1,   g_ff1);
    cudaGetSymbolAddress((void**)&wqkTH, g_wqkTH);
    cudaGetSymbolAddress((void**)&wqkTL, g_wqkTL);
    cudaGetSymbolAddress((void**)&wvT,   g_wvT);
    cudaGetSymbolAddress((void**)&woT,   g_woT);
    cudaGetSymbolAddress((void**)&w1T,   g_w1T);
    cudaGetSymbolAddress((void**)&w2T,   g_w2T);

    cudaFuncSetAttribute(qk_gemm, cudaFuncAttributeMaxDynamicSharedMemorySize, QSMEM_BYTES);
    cudaFuncSetAttribute(hgemm<1024,1024,1,5>, cudaFuncAttributeMaxDynamicSharedMemorySize, HSMEM(5));
    cudaFuncSetAttribute(hgemm<1024,1024,3,5>, cudaFuncAttributeMaxDynamicSharedMemorySize, HSMEM(5));
    cudaFuncSetAttribute(hgemm<4096,1024,2,4>, cudaFuncAttributeMaxDynamicSharedMemorySize, HSMEM(4));
    cudaFuncSetAttribute(hgemm<1024,4096,1,4>, cudaFuncAttributeMaxDynamicSharedMemorySize, HSMEM(4));
    cudaFuncSetAttribute(flash_kernel, cudaFuncAttributeMaxDynamicSharedMemorySize, FSMEM_BYTES);

    dim3 tb(32, 8);
    // 0. LN1 -> fp16 + bf16 hi/lo
    ln_kernel<1><<<NTOK, 256>>>(x, g1, be1, ln16, lnH, lnL);
    // 1. all weight transposes (one launch)
    transpose_all_kernel<<<12288, tb>>>(Wq, Wk, Wv, Wo, W1, W2,
                                        wqkTH, wqkTL, wvT, woT, w1T, w2T);
    // 2. Q,K projection (bf16x3); Q pre-scaled by log2e
    qk_gemm<<<dim3(16, 64), 512, QSMEM_BYTES>>>(
        (__nv_bfloat16*)lnH, (__nv_bfloat16*)lnL, wqkTH, wqkTL, qH, qL,
        (uint32_t*)kH, (uint32_t*)kL);
    // 3. V projection (fp16, 5-stage) -> V^T fp16
    hgemm<1024,1024,3,5><<<dim3(8, 64), 512, HSMEM(5)>>>(
        ln16, (const uint32_t*)wvT, vT, nullptr, nullptr);
    // 4. flash attention -> concat heads (fp16)
    flash_kernel<<<dim3(16, 64), 256, FSMEM_BYTES>>>(qH, qL, kH, kL, (uint32_t*)vT, attnc);
    // 5. x1 = x + attnc @ Wo + bo   (5-stage)
    hgemm<1024,1024,1,5><<<dim3(8, 64), 512, HSMEM(5)>>>(
        attnc, (const uint32_t*)woT, x1, bo, x);
    // 6. LN2 -> fp16
    ln_kernel<0><<<NTOK, 256>>>(x1, g2, be2, lnH2, nullptr, nullptr);
    // 7. ff1 = relu(ln2 @ W1 + b1)  (4-stage, R15 config)
    hgemm<4096,1024,2,4><<<dim3(32, 64), 512, HSMEM(4)>>>(
        lnH2, (const uint32_t*)w1T, ff1, b1, nullptr);
    // 8. out = x1 + ff1 @ W2 + b2   (4-stage, R15 config)
    hgemm<1024,4096,1,4><<<dim3(8, 64), 512, HSMEM(4)>>>(
        ff1, (const uint32_t*)w2T, out, b2, x1);
}